// round 11
// baseline (speedup 1.0000x reference)
#include <cuda_runtime.h>
#include <cuda_bf16.h>
#include <math.h>

#define Hdim 256
#define Wdim 256
#define HW   65536
#define CC   12
#define BB   8
#define BC   96
#define SENT 600        // sentinel: 600^2 = 360000 > max real d^2 (130050)

// Scratch (device globals; no allocation allowed)
__device__ unsigned short g_vU[BC * HW]; // up-scan:  dist-to-zero above | (fg<<15)
__device__ unsigned short g_vD[BC * HW]; // down-scan: dist-to-zero below
__device__ float g_dt  [BC * HW];        // signed distance dt = neg - pos
__device__ int   g_hasfg[BC * 2];        // per column-half flags (plain stores)
__device__ float g_minmax[BC * 2];       // (min, max) per bc  -- atomic
__device__ float g_dsum  [BC * 2];       // (sum d, sum d^2)    -- atomic
__device__ float g_sums  [BC * 3];       // (sum p*d, sum p, sum p^2)
__device__ unsigned g_ctr;               // k_sums completion counter

__device__ __forceinline__ float atomicMinFloat(float* a, float v) {
    return (v >= 0.0f)
        ? __int_as_float(atomicMin((int*)a, __float_as_int(v)))
        : __uint_as_float(atomicMax((unsigned*)a, __float_as_uint(v)));
}
__device__ __forceinline__ float atomicMaxFloat(float* a, float v) {
    return (v >= 0.0f)
        ? __int_as_float(atomicMax((int*)a, __float_as_int(v)))
        : __uint_as_float(atomicMin((unsigned*)a, __float_as_uint(v)));
}

// ---------------------------------------------------------------------------
// K1: vertical 1D distance per column. Task = (bc, dir, column-half):
// 384 blocks x 128 threads for SM load balance (max 12 warps/SM vs 16).
// Single-tracker scan: d = (kind changed vs previous row) ? 1 : min(d+1,SENT);
// first row in scan direction = SENT. For pixel of kind K the nearest
// opposite pixel along the scan is exactly the last kind-change location.
// Down-scan also stores the fg flag (bit 15) + per-half hasfg flags.
// Block 0 resets the atomic accumulators (consumed only downstream).
// ---------------------------------------------------------------------------
__global__ void __launch_bounds__(128) k_vert(const int* __restrict__ targets) {
    const int task = blockIdx.x;
    const int bc   = task >> 2;
    const int dir  = (task >> 1) & 1;
    const int half = task & 1;
    const int b = bc / CC, c = bc % CC;
    const int w = (half << 7) | threadIdx.x;
    const int* tb = targets + b * HW;

    if (task == 0) {
        const int i = threadIdx.x;
        if (i < BC) {
            g_minmax[i * 2]     =  1e30f;
            g_minmax[i * 2 + 1] = -1e30f;
        }
        for (int k = i; k < BC * 3; k += 128) g_sums[k] = 0.0f;
        for (int k = i; k < BC * 2; k += 128) g_dsum[k] = 0.0f;
        if (i == 0) g_ctr = 0u;
    }

    if (dir == 0) {
        unsigned short* V = g_vU + bc * HW;
        int prevfg = (tb[w] == c);
        int anyfg  = prevfg;
        V[w] = (unsigned short)(SENT | (prevfg << 15));
        int d = SENT;
        #pragma unroll 16
        for (int h = 1; h < Hdim; ++h) {
            const int fg = (tb[h * Wdim + w] == c);
            anyfg |= fg;
            d = (fg != prevfg) ? 1 : min(d + 1, SENT);
            prevfg = fg;
            V[h * Wdim + w] = (unsigned short)(d | (fg << 15));
        }
        const int blkfg = __syncthreads_or(anyfg);
        if (threadIdx.x == 0) g_hasfg[bc * 2 + half] = blkfg;
    } else {
        unsigned short* V = g_vD + bc * HW;
        int prevfg = (tb[(Hdim - 1) * Wdim + w] == c);
        V[(Hdim - 1) * Wdim + w] = (unsigned short)SENT;
        int d = SENT;
        #pragma unroll 16
        for (int h = Hdim - 2; h >= 0; --h) {
            const int fg = (tb[h * Wdim + w] == c);
            d = (fg != prevfg) ? 1 : min(d + 1, SENT);
            prevfg = fg;
            V[h * Wdim + w] = (unsigned short)d;
        }
    }
}

// ---------------------------------------------------------------------------
// K2: horizontal exact min-plus, 4 ROWS PER BLOCK (sequential per thread).
//   d2(j) = min_k (j-k)^2 + g2[k];  stop when r^2 >= best (exact).
// Probe indices clamped to [0,255] (clamped reads only over-estimate; the
// true edge candidate is probed exactly at r=|j-edge|, so still exact).
// Fill: one coalesced pass over all 4 rows; one __syncthreads; per-thread
// search x4 with min/max/sum/sum2 accumulated in registers; ONE block
// reduction + 4 atomics per 4 rows.
// ---------------------------------------------------------------------------
__global__ void __launch_bounds__(256) k_hmin() {
    const int row0 = blockIdx.x << 2;      // first of 4 rows (same bc: 256|4)
    const int bc   = row0 >> 8;
    const int j    = threadIdx.x;

    __shared__ float shP[4][256];
    __shared__ float shN[4][256];

    int   fgr [4];
    float fsqr[4];
    #pragma unroll
    for (int r = 0; r < 4; ++r) {
        const int gi = (row0 + r) * Wdim + j;
        const unsigned vu = g_vU[gi];
        const unsigned vd = g_vD[gi];
        const int   fgk = (int)(vu >> 15);
        const float dd  = (float)min((int)(vu & 0x7fffu), (int)vd);
        const float sq  = dd * dd;
        shP[r][j] = fgk ? sq : 0.0f;
        shN[r][j] = fgk ? 0.0f : sq;
        fgr [r] = fgk;
        fsqr[r] = sq;
    }
    const int hf = g_hasfg[bc * 2] | g_hasfg[bc * 2 + 1];
    __syncthreads();

    float mn = 1e30f, mx = -1e30f, sd = 0.0f, sd2 = 0.0f;
    #pragma unroll
    for (int r = 0; r < 4; ++r) {
        const float* s = fgr[r] ? shP[r] : shN[r];
        float best = fsqr[r];
        float rr = 1.0f, dr = 3.0f;
        #pragma unroll 1
        for (int t = 1; t < 256; ++t) {
            if (rr >= best) break;
            const int kl = max(j - t, 0);
            const int kr = min(j + t, 255);
            best = fminf(best, rr + s[kl]);
            best = fminf(best, rr + s[kr]);
            rr += dr; dr += 2.0f;
        }
        float dt = fgr[r] ? -sqrtf(best) : sqrtf(best);
        if (!hf) dt = 0.0f;
        g_dt[(row0 + r) * Wdim + j] = dt;
        mn  = fminf(mn, dt);
        mx  = fmaxf(mx, dt);
        sd  += dt;
        sd2 += dt * dt;
    }

    // one fused block reduction per 4 rows: min, max, sum, sum2 -> 4 atomics
    #pragma unroll
    for (int o = 16; o; o >>= 1) {
        mn  = fminf(mn, __shfl_xor_sync(0xffffffffu, mn, o));
        mx  = fmaxf(mx, __shfl_xor_sync(0xffffffffu, mx, o));
        sd  += __shfl_xor_sync(0xffffffffu, sd,  o);
        sd2 += __shfl_xor_sync(0xffffffffu, sd2, o);
    }
    __shared__ float red[4][8];
    const int wid = j >> 5, lane = j & 31;
    if (lane == 0) { red[0][wid] = mn; red[1][wid] = mx; red[2][wid] = sd; red[3][wid] = sd2; }
    __syncthreads();
    if (j == 0) {
        mn = red[0][0]; mx = red[1][0]; sd = red[2][0]; sd2 = red[3][0];
        #pragma unroll
        for (int i = 1; i < 8; ++i) {
            mn  = fminf(mn, red[0][i]);
            mx  = fmaxf(mx, red[1][i]);
            sd  += red[2][i];
            sd2 += red[3][i];
        }
        atomicMinFloat(&g_minmax[bc * 2],     mn);
        atomicMaxFloat(&g_minmax[bc * 2 + 1], mx);
        atomicAdd(&g_dsum[bc * 2],     sd);
        atomicAdd(&g_dsum[bc * 2 + 1], sd2);
    }
}

// ---------------------------------------------------------------------------
// K3: fused softmax + raw dice moments + (last block) final loss.
//   Spd = sum p*dt,  Sp = sum p,  Sp2 = sum p^2   per class (no normalize).
// Grid: (b, 64 row-groups) = 512 blocks; thread handles one column x 4 rows.
// Last finishing block reconstructs normalized sums and writes the loss:
//   inter = inv*(Spd - dmin*Sp)
//   D2    = inv^2*(Sd2 - 2*dmin*Sd + N*dmin^2)
// ---------------------------------------------------------------------------
__global__ void __launch_bounds__(256, 3) k_sums(const float* __restrict__ logits,
                                                 float* __restrict__ out) {
    const int blk = blockIdx.x;            // b*64 + rowgroup
    const int b   = blk >> 6;
    const int h0  = (blk & 63) * 4;
    const int w   = threadIdx.x;

    float aI[CC], aS[CC], aP2[CC];
    #pragma unroll
    for (int c = 0; c < CC; ++c) { aI[c] = 0.0f; aS[c] = 0.0f; aP2[c] = 0.0f; }

    const int boffL = b * CC * HW;
    for (int r = 0; r < 4; ++r) {
        const int pix = (h0 + r) * Wdim + w;
        float l[CC];
        float mxl = -1e30f;
        #pragma unroll
        for (int c = 0; c < CC; ++c) {
            l[c] = logits[boffL + c * HW + pix];
            mxl = fmaxf(mxl, l[c]);
        }
        float s = 0.0f;
        #pragma unroll
        for (int c = 0; c < CC; ++c) { l[c] = __expf(l[c] - mxl); s += l[c]; }
        const float rs = 1.0f / s;
        #pragma unroll
        for (int c = 0; c < CC; ++c) {
            const float p = l[c] * rs;
            const float dd = g_dt[boffL + c * HW + pix];
            aI [c] = fmaf(p, dd, aI [c]);
            aS [c] += p;
            aP2[c] = fmaf(p, p, aP2[c]);
        }
    }

    #pragma unroll
    for (int c = 0; c < CC; ++c) {
        #pragma unroll
        for (int o = 16; o; o >>= 1) {
            aI [c] += __shfl_xor_sync(0xffffffffu, aI [c], o);
            aS [c] += __shfl_xor_sync(0xffffffffu, aS [c], o);
            aP2[c] += __shfl_xor_sync(0xffffffffu, aP2[c], o);
        }
    }
    __shared__ float sred[36][8];
    const int lane = w & 31, wi = w >> 5;
    if (lane == 0) {
        #pragma unroll
        for (int c = 0; c < CC; ++c) {
            sred[c * 3 + 0][wi] = aI [c];
            sred[c * 3 + 1][wi] = aS [c];
            sred[c * 3 + 2][wi] = aP2[c];
        }
    }
    __syncthreads();
    if (w < 36) {
        float acc = 0.0f;
        #pragma unroll
        for (int i = 0; i < 8; ++i) acc += sred[w][i];
        const int c    = w / 3;
        const int comp = w - c * 3;
        atomicAdd(&g_sums[(b * CC + c) * 3 + comp], acc);
    }

    // ---- last-block-done: compute the final loss, no extra launch ----
    __threadfence();
    __shared__ unsigned done;
    if (w == 0) done = atomicAdd(&g_ctr, 1u);
    __syncthreads();
    if (done == gridDim.x - 1) {
        __threadfence();
        __shared__ float sfin[BC];
        if (w < BC) {
            const float dmin = g_minmax[w * 2];
            const float dmax = g_minmax[w * 2 + 1];
            const float inv  = 1.0f / (dmax - dmin + 1e-8f);
            const float Spd  = g_sums[w * 3];
            const float Sp   = g_sums[w * 3 + 1];
            const float Sp2  = g_sums[w * 3 + 2];
            const float Sd   = g_dsum[w * 2];
            const float Sd2  = g_dsum[w * 2 + 1];
            const float I  = inv * (Spd - dmin * Sp);
            const float D2 = inv * inv * (Sd2 - 2.0f * dmin * Sd + 65536.0f * dmin * dmin);
            sfin[w] = 1.0f - 2.0f * I / (Sp2 + D2 + 1e-6f);
        }
        __syncthreads();
        if (w == 0) {
            float acc = 0.0f;
            #pragma unroll
            for (int i = 0; i < BC; ++i) acc += sfin[i];
            out[0] = acc / (float)BC;
        }
    }
}

extern "C" void kernel_launch(void* const* d_in, const int* in_sizes, int n_in,
                              void* d_out, int out_size) {
    const float* logits  = (const float*)d_in[0];
    const int*   targets = (const int*)d_in[1];
    float* out = (float*)d_out;

    k_vert <<<BC * 4, 128>>>(targets);
    k_hmin <<<BC * Hdim / 4, 256>>>();
    k_sums <<<BB * 64, 256>>>(logits, out);
}

// round 12
// speedup vs baseline: 1.2247x; 1.2247x over previous
#include <cuda_runtime.h>
#include <cuda_bf16.h>
#include <math.h>

#define Hdim 256
#define Wdim 256
#define HW   65536
#define CC   12
#define BB   8
#define BC   96
#define SENT 600        // sentinel: 600^2 = 360000 > max real d^2 (130050)

// dt quantization: q = (dt + 512) * 64, decode dt = q/64 - 512.
// |dt| <= 360.63 -> q in [9688, 55848] fits u16; step 1/64.
#define DTQ_SCALE 64.0f
#define DTQ_INV   0.015625f
#define DTQ_OFF   512.0f

// Scratch (device globals; no allocation allowed)
__device__ unsigned short g_vU[BC * HW]; // up-scan:  dist-to-zero above | (fg<<15)
__device__ unsigned short g_vD[BC * HW]; // down-scan: dist-to-zero below
__device__ unsigned short g_dtq[BC * HW];// quantized signed distance
__device__ int   g_hasfg[BC];
__device__ float g_minmax[BC * 2];       // (min, max) per bc  -- atomic
__device__ float g_dsum  [BC * 2];       // (sum d, sum d^2)    -- atomic
__device__ float g_sums  [BC * 3];       // (sum p*d, sum p, sum p^2)
__device__ unsigned g_ctr;               // k_sums completion counter

__device__ __forceinline__ float atomicMinFloat(float* a, float v) {
    return (v >= 0.0f)
        ? __int_as_float(atomicMin((int*)a, __float_as_int(v)))
        : __uint_as_float(atomicMax((unsigned*)a, __float_as_uint(v)));
}
__device__ __forceinline__ float atomicMaxFloat(float* a, float v) {
    return (v >= 0.0f)
        ? __int_as_float(atomicMax((int*)a, __float_as_int(v)))
        : __uint_as_float(atomicMin((unsigned*)a, __float_as_uint(v)));
}

// ---------------------------------------------------------------------------
// K1 (R10-proven): vertical 1D distance per column, split into TWO
// INDEPENDENT blocks per (b,c): even block = down-scan (dist to nearest
// zero at-or-above + fg flag + hasfg + accumulator init), odd block =
// up-scan (dist to nearest zero at-or-below). k_hmin combines with min().
// ---------------------------------------------------------------------------
__global__ void __launch_bounds__(256) k_vert(const int* __restrict__ targets) {
    const int bc  = blockIdx.x >> 1;
    const int dir = blockIdx.x & 1;
    const int b   = bc / CC, c = bc % CC;
    const int w   = threadIdx.x;
    const int* tb = targets + b * HW;

    if (blockIdx.x == 0) {
        if (w < BC) {
            g_minmax[w * 2]     =  1e30f;
            g_minmax[w * 2 + 1] = -1e30f;
        }
        if (w < BC * 2) g_dsum[w] = 0.0f;
        for (int k = w; k < BC * 3; k += 256) g_sums[k] = 0.0f;
        if (w == 0) g_ctr = 0u;
    }

    if (dir == 0) {
        unsigned short* V = g_vU + bc * HW;
        int upP = -100000;   // last bg row (zero of m)
        int upN = -100000;   // last fg row (zero of ~m)
        int anyfg = 0;
        #pragma unroll 16
        for (int h = 0; h < Hdim; ++h) {
            const int fg = (tb[h * Wdim + w] == c);
            anyfg |= fg;
            if (!fg) upP = h;
            else     upN = h;
            const int d = fg ? min(h - upP, SENT) : min(h - upN, SENT);
            V[h * Wdim + w] = (unsigned short)(d | (fg << 15));
        }
        const int blkfg = __syncthreads_or(anyfg);
        if (w == 0) g_hasfg[bc] = blkfg;
    } else {
        unsigned short* V = g_vD + bc * HW;
        int dnP = 100000, dnN = 100000;
        #pragma unroll 16
        for (int h = Hdim - 1; h >= 0; --h) {
            const int fg = (tb[h * Wdim + w] == c);
            if (!fg) dnP = h;
            else     dnN = h;
            const int d = fg ? min(dnP - h, SENT) : min(dnN - h, SENT);
            V[h * Wdim + w] = (unsigned short)d;
        }
    }
}

// ---------------------------------------------------------------------------
// K2: horizontal exact min-plus, 4 ROWS PER BLOCK (sequential per thread).
//   d2(j) = min_k (j-k)^2 + g2[k];  stop when r^2 >= best (exact).
// Probe indices clamped to [0,255] (clamped reads only over-estimate; the
// true edge candidate is probed exactly at r=|j-edge|, so still exact).
// dt is quantized to u16 fixed point; the SAME dequantized value feeds the
// min/max/sum/sum2 reduction so the k_final algebra is self-consistent.
// ---------------------------------------------------------------------------
__global__ void __launch_bounds__(256) k_hmin() {
    const int row0 = blockIdx.x << 2;      // first of 4 rows (same bc: 256|4)
    const int bc   = row0 >> 8;
    const int j    = threadIdx.x;

    __shared__ float shP[4][256];
    __shared__ float shN[4][256];

    int   fgr [4];
    float fsqr[4];
    #pragma unroll
    for (int r = 0; r < 4; ++r) {
        const int gi = (row0 + r) * Wdim + j;
        const unsigned vu = g_vU[gi];
        const unsigned vd = g_vD[gi];
        const int   fgk = (int)(vu >> 15);
        const float dd  = (float)min((int)(vu & 0x7fffu), (int)vd);
        const float sq  = dd * dd;
        shP[r][j] = fgk ? sq : 0.0f;
        shN[r][j] = fgk ? 0.0f : sq;
        fgr [r] = fgk;
        fsqr[r] = sq;
    }
    const int hf = g_hasfg[bc];
    __syncthreads();

    float mn = 1e30f, mx = -1e30f, sd = 0.0f, sd2 = 0.0f;
    #pragma unroll
    for (int r = 0; r < 4; ++r) {
        const float* s = fgr[r] ? shP[r] : shN[r];
        float best = fsqr[r];
        float rr = 1.0f, dr = 3.0f;
        #pragma unroll 1
        for (int t = 1; t < 256; ++t) {
            if (rr >= best) break;
            const int kl = max(j - t, 0);
            const int kr = min(j + t, 255);
            best = fminf(best, rr + s[kl]);
            best = fminf(best, rr + s[kr]);
            rr += dr; dr += 2.0f;
        }
        float dt = fgr[r] ? -sqrtf(best) : sqrtf(best);
        if (!hf) dt = 0.0f;
        // quantize; use the dequantized value for ALL downstream math
        const unsigned q = __float2uint_rn((dt + DTQ_OFF) * DTQ_SCALE);
        g_dtq[(row0 + r) * Wdim + j] = (unsigned short)q;
        const float dv = (float)q * DTQ_INV - DTQ_OFF;
        mn  = fminf(mn, dv);
        mx  = fmaxf(mx, dv);
        sd  += dv;
        sd2 += dv * dv;
    }

    // one fused block reduction per 4 rows: min, max, sum, sum2 -> 4 atomics
    #pragma unroll
    for (int o = 16; o; o >>= 1) {
        mn  = fminf(mn, __shfl_xor_sync(0xffffffffu, mn, o));
        mx  = fmaxf(mx, __shfl_xor_sync(0xffffffffu, mx, o));
        sd  += __shfl_xor_sync(0xffffffffu, sd,  o);
        sd2 += __shfl_xor_sync(0xffffffffu, sd2, o);
    }
    __shared__ float red[4][8];
    const int wid = j >> 5, lane = j & 31;
    if (lane == 0) { red[0][wid] = mn; red[1][wid] = mx; red[2][wid] = sd; red[3][wid] = sd2; }
    __syncthreads();
    if (j == 0) {
        mn = red[0][0]; mx = red[1][0]; sd = red[2][0]; sd2 = red[3][0];
        #pragma unroll
        for (int i = 1; i < 8; ++i) {
            mn  = fminf(mn, red[0][i]);
            mx  = fmaxf(mx, red[1][i]);
            sd  += red[2][i];
            sd2 += red[3][i];
        }
        atomicMinFloat(&g_minmax[bc * 2],     mn);
        atomicMaxFloat(&g_minmax[bc * 2 + 1], mx);
        atomicAdd(&g_dsum[bc * 2],     sd);
        atomicAdd(&g_dsum[bc * 2 + 1], sd2);
    }
}

// ---------------------------------------------------------------------------
// K3: fused softmax + raw dice moments + (last block) final loss.
//   Spd = sum p*dt,  Sp = sum p,  Sp2 = sum p^2   per class (no normalize).
// Grid: (b, 64 row-groups) = 512 blocks; thread handles one column x 4 rows.
// dt read as u16 and dequantized (identical value to k_hmin's reduction).
// Last finishing block reconstructs normalized sums and writes the loss.
// ---------------------------------------------------------------------------
__global__ void __launch_bounds__(256, 3) k_sums(const float* __restrict__ logits,
                                                 float* __restrict__ out) {
    const int blk = blockIdx.x;            // b*64 + rowgroup
    const int b   = blk >> 6;
    const int h0  = (blk & 63) * 4;
    const int w   = threadIdx.x;

    float aI[CC], aS[CC], aP2[CC];
    #pragma unroll
    for (int c = 0; c < CC; ++c) { aI[c] = 0.0f; aS[c] = 0.0f; aP2[c] = 0.0f; }

    const int boffL = b * CC * HW;
    for (int r = 0; r < 4; ++r) {
        const int pix = (h0 + r) * Wdim + w;
        float l[CC];
        float mxl = -1e30f;
        #pragma unroll
        for (int c = 0; c < CC; ++c) {
            l[c] = logits[boffL + c * HW + pix];
            mxl = fmaxf(mxl, l[c]);
        }
        float s = 0.0f;
        #pragma unroll
        for (int c = 0; c < CC; ++c) { l[c] = __expf(l[c] - mxl); s += l[c]; }
        const float rs = 1.0f / s;
        #pragma unroll
        for (int c = 0; c < CC; ++c) {
            const float p  = l[c] * rs;
            const float dd = (float)g_dtq[boffL + c * HW + pix] * DTQ_INV - DTQ_OFF;
            aI [c] = fmaf(p, dd, aI [c]);
            aS [c] += p;
            aP2[c] = fmaf(p, p, aP2[c]);
        }
    }

    #pragma unroll
    for (int c = 0; c < CC; ++c) {
        #pragma unroll
        for (int o = 16; o; o >>= 1) {
            aI [c] += __shfl_xor_sync(0xffffffffu, aI [c], o);
            aS [c] += __shfl_xor_sync(0xffffffffu, aS [c], o);
            aP2[c] += __shfl_xor_sync(0xffffffffu, aP2[c], o);
        }
    }
    __shared__ float sred[36][8];
    const int lane = w & 31, wi = w >> 5;
    if (lane == 0) {
        #pragma unroll
        for (int c = 0; c < CC; ++c) {
            sred[c * 3 + 0][wi] = aI [c];
            sred[c * 3 + 1][wi] = aS [c];
            sred[c * 3 + 2][wi] = aP2[c];
        }
    }
    __syncthreads();
    if (w < 36) {
        float acc = 0.0f;
        #pragma unroll
        for (int i = 0; i < 8; ++i) acc += sred[w][i];
        const int c    = w / 3;
        const int comp = w - c * 3;
        atomicAdd(&g_sums[(b * CC + c) * 3 + comp], acc);
    }

    // ---- last-block-done: compute the final loss, no extra launch ----
    __threadfence();
    __shared__ unsigned done;
    if (w == 0) done = atomicAdd(&g_ctr, 1u);
    __syncthreads();
    if (done == gridDim.x - 1) {
        __threadfence();
        __shared__ float sfin[BC];
        if (w < BC) {
            const float dmin = g_minmax[w * 2];
            const float dmax = g_minmax[w * 2 + 1];
            const float inv  = 1.0f / (dmax - dmin + 1e-8f);
            const float Spd  = g_sums[w * 3];
            const float Sp   = g_sums[w * 3 + 1];
            const float Sp2  = g_sums[w * 3 + 2];
            const float Sd   = g_dsum[w * 2];
            const float Sd2  = g_dsum[w * 2 + 1];
            const float I  = inv * (Spd - dmin * Sp);
            const float D2 = inv * inv * (Sd2 - 2.0f * dmin * Sd + 65536.0f * dmin * dmin);
            sfin[w] = 1.0f - 2.0f * I / (Sp2 + D2 + 1e-6f);
        }
        __syncthreads();
        if (w == 0) {
            float acc = 0.0f;
            #pragma unroll
            for (int i = 0; i < BC; ++i) acc += sfin[i];
            out[0] = acc / (float)BC;
        }
    }
}

extern "C" void kernel_launch(void* const* d_in, const int* in_sizes, int n_in,
                              void* d_out, int out_size) {
    const float* logits  = (const float*)d_in[0];
    const int*   targets = (const int*)d_in[1];
    float* out = (float*)d_out;

    k_vert <<<BC * 2, 256>>>(targets);
    k_hmin <<<BC * Hdim / 4, 256>>>();
    k_sums <<<BB * 64, 256>>>(logits, out);
}

// round 14
// speedup vs baseline: 1.4348x; 1.1716x over previous
#include <cuda_runtime.h>
#include <cuda_bf16.h>
#include <math.h>

#define Hdim 256
#define Wdim 256
#define HW   65536
#define CC   12
#define BB   8
#define BC   96
#define SENT 600        // sentinel: 600^2 = 360000 > max real d^2 (130050)

#define PQ_SCALE 65535.0f
#define PQ_INV   (1.0f / 65535.0f)

// Scratch (device globals; no allocation allowed).
// Accumulators are ZERO-initialized at module load and reset to zero by the
// last k_main block each run -> every graph replay sees identical state.
__device__ unsigned short g_vU[BC * HW]; // up-scan:  dist | (fg<<15)
__device__ unsigned short g_vD[BC * HW]; // down-scan: dist
__device__ unsigned short g_p [BC * HW]; // quantized softmax probs
__device__ int   g_hasfg[BC];            // plain stores, rewritten each run
__device__ float g_minmax[BC * 2];       // (min<=0, max>=0) per bc -- atomic
__device__ float g_dsum  [BC * 3];       // (sum d, sum d^2, sum p*d) -- atomic
__device__ float g_sums  [BC * 2];       // (sum p, sum p^2) -- atomic
__device__ unsigned g_ctr;               // k_main completion counter

__device__ __forceinline__ float atomicMinFloat(float* a, float v) {
    return (v >= 0.0f)
        ? __int_as_float(atomicMin((int*)a, __float_as_int(v)))
        : __uint_as_float(atomicMax((unsigned*)a, __float_as_uint(v)));
}
__device__ __forceinline__ float atomicMaxFloat(float* a, float v) {
    return (v >= 0.0f)
        ? __int_as_float(atomicMax((int*)a, __float_as_int(v)))
        : __uint_as_float(atomicMin((unsigned*)a, __float_as_uint(v)));
}

// ---------------------------------------------------------------------------
// K1: fused "preparation" kernel, 448 blocks.
//  blocks [0,192):   vertical 1D distance scans (R10-proven: (bc, dir) split,
//                    down-scan stores dist|fg<<15 + hasfg, up-scan stores dist)
//  blocks [192,448): softmax over C per pixel; stores p as u16 fixed point and
//                    accumulates exact fp32 Sp, Sp2 per (b,c) via atomics.
// The two halves are independent and overlap on the SMs within one launch.
// ---------------------------------------------------------------------------
__global__ void __launch_bounds__(256) k_pre(const int* __restrict__ targets,
                                             const float* __restrict__ logits) {
    if (blockIdx.x < BC * 2) {
        const int bc  = blockIdx.x >> 1;
        const int dir = blockIdx.x & 1;
        const int b   = bc / CC, c = bc % CC;
        const int w   = threadIdx.x;
        const int* tb = targets + b * HW;

        if (dir == 0) {
            unsigned short* V = g_vU + bc * HW;
            int upP = -100000;   // last bg row (zero of m)
            int upN = -100000;   // last fg row (zero of ~m)
            int anyfg = 0;
            #pragma unroll 16
            for (int h = 0; h < Hdim; ++h) {
                const int fg = (tb[h * Wdim + w] == c);
                anyfg |= fg;
                if (!fg) upP = h;
                else     upN = h;
                const int d = fg ? min(h - upP, SENT) : min(h - upN, SENT);
                V[h * Wdim + w] = (unsigned short)(d | (fg << 15));
            }
            const int blkfg = __syncthreads_or(anyfg);
            if (w == 0) g_hasfg[bc] = blkfg;
        } else {
            unsigned short* V = g_vD + bc * HW;
            int dnP = 100000, dnN = 100000;
            #pragma unroll 16
            for (int h = Hdim - 1; h >= 0; --h) {
                const int fg = (tb[h * Wdim + w] == c);
                if (!fg) dnP = h;
                else     dnN = h;
                const int d = fg ? min(dnP - h, SENT) : min(dnN - h, SENT);
                V[h * Wdim + w] = (unsigned short)d;
            }
        }
    } else {
        const int blkp = blockIdx.x - BC * 2;  // b*32 + rowgroup
        const int b    = blkp >> 5;
        const int h0   = (blkp & 31) * 8;
        const int w    = threadIdx.x;

        float aS[CC], aP2[CC];
        #pragma unroll
        for (int c = 0; c < CC; ++c) { aS[c] = 0.0f; aP2[c] = 0.0f; }

        const int boff = b * CC * HW;
        for (int r = 0; r < 8; ++r) {
            const int pix = (h0 + r) * Wdim + w;
            float l[CC];
            float mxl = -1e30f;
            #pragma unroll
            for (int c = 0; c < CC; ++c) {
                l[c] = logits[boff + c * HW + pix];
                mxl = fmaxf(mxl, l[c]);
            }
            float s = 0.0f;
            #pragma unroll
            for (int c = 0; c < CC; ++c) { l[c] = __expf(l[c] - mxl); s += l[c]; }
            const float rs = 1.0f / s;
            #pragma unroll
            for (int c = 0; c < CC; ++c) {
                const float p = l[c] * rs;
                g_p[boff + c * HW + pix] =
                    (unsigned short)__float2uint_rn(p * PQ_SCALE);
                aS [c] += p;
                aP2[c] = fmaf(p, p, aP2[c]);
            }
        }

        #pragma unroll
        for (int c = 0; c < CC; ++c) {
            #pragma unroll
            for (int o = 16; o; o >>= 1) {
                aS [c] += __shfl_xor_sync(0xffffffffu, aS [c], o);
                aP2[c] += __shfl_xor_sync(0xffffffffu, aP2[c], o);
            }
        }
        __shared__ float sred[24][8];
        const int lane = w & 31, wi = w >> 5;
        if (lane == 0) {
            #pragma unroll
            for (int c = 0; c < CC; ++c) {
                sred[c * 2 + 0][wi] = aS [c];
                sred[c * 2 + 1][wi] = aP2[c];
            }
        }
        __syncthreads();
        if (w < 24) {
            float acc = 0.0f;
            #pragma unroll
            for (int i = 0; i < 8; ++i) acc += sred[w][i];
            atomicAdd(&g_sums[(b * CC + (w >> 1)) * 2 + (w & 1)], acc);
        }
    }
}

// ---------------------------------------------------------------------------
// K2: horizontal exact min-plus, 4 rows/block; dt lives only in registers.
//   d2(j) = min_k (j-k)^2 + g2[k];  stop when r^2 >= best (exact; clamped
//   probe indices only over-estimate, true edge candidate hit at r=|j-edge|).
// Per thread accumulates min, max, sum d, sum d^2, sum p*d (p from g_p);
// one block reduction + 5 atomics per 4 rows. Last finishing block computes
// the loss and resets ALL accumulators (strided loops — full coverage!)
// so every graph replay sees identical state.
// ---------------------------------------------------------------------------
__global__ void __launch_bounds__(256) k_main(float* __restrict__ out) {
    const int row0 = blockIdx.x << 2;      // first of 4 rows (same bc: 256|4)
    const int bc   = row0 >> 8;
    const int j    = threadIdx.x;

    __shared__ float shP[4][256];
    __shared__ float shN[4][256];

    int   fgr [4];
    float fsqr[4], pv[4];
    #pragma unroll
    for (int r = 0; r < 4; ++r) {
        const int gi = (row0 + r) * Wdim + j;
        const unsigned vu = g_vU[gi];
        const unsigned vd = g_vD[gi];
        const int   fgk = (int)(vu >> 15);
        const float dd  = (float)min((int)(vu & 0x7fffu), (int)vd);
        const float sq  = dd * dd;
        shP[r][j] = fgk ? sq : 0.0f;
        shN[r][j] = fgk ? 0.0f : sq;
        fgr [r] = fgk;
        fsqr[r] = sq;
        pv  [r] = (float)g_p[gi] * PQ_INV;
    }
    const int hf = g_hasfg[bc];
    __syncthreads();

    float mn = 0.0f, mx = 0.0f, sd = 0.0f, sd2 = 0.0f, spd = 0.0f;
    #pragma unroll
    for (int r = 0; r < 4; ++r) {
        const float* s = fgr[r] ? shP[r] : shN[r];
        float best = fsqr[r];
        float rr = 1.0f, dr = 3.0f;
        #pragma unroll 1
        for (int t = 1; t < 256; ++t) {
            if (rr >= best) break;
            const int kl = max(j - t, 0);
            const int kr = min(j + t, 255);
            best = fminf(best, rr + s[kl]);
            best = fminf(best, rr + s[kr]);
            rr += dr; dr += 2.0f;
        }
        float dt = fgr[r] ? -sqrtf(best) : sqrtf(best);
        if (!hf) dt = 0.0f;
        mn  = fminf(mn, dt);
        mx  = fmaxf(mx, dt);
        sd  += dt;
        sd2 += dt * dt;
        spd = fmaf(pv[r], dt, spd);
    }

    #pragma unroll
    for (int o = 16; o; o >>= 1) {
        mn  = fminf(mn, __shfl_xor_sync(0xffffffffu, mn, o));
        mx  = fmaxf(mx, __shfl_xor_sync(0xffffffffu, mx, o));
        sd  += __shfl_xor_sync(0xffffffffu, sd,  o);
        sd2 += __shfl_xor_sync(0xffffffffu, sd2, o);
        spd += __shfl_xor_sync(0xffffffffu, spd, o);
    }
    __shared__ float red[5][8];
    const int wid = j >> 5, lane = j & 31;
    if (lane == 0) {
        red[0][wid] = mn; red[1][wid] = mx;
        red[2][wid] = sd; red[3][wid] = sd2; red[4][wid] = spd;
    }
    __syncthreads();
    if (j == 0) {
        mn = red[0][0]; mx = red[1][0]; sd = red[2][0]; sd2 = red[3][0]; spd = red[4][0];
        #pragma unroll
        for (int i = 1; i < 8; ++i) {
            mn  = fminf(mn, red[0][i]);
            mx  = fmaxf(mx, red[1][i]);
            sd  += red[2][i];
            sd2 += red[3][i];
            spd += red[4][i];
        }
        atomicMinFloat(&g_minmax[bc * 2],     mn);
        atomicMaxFloat(&g_minmax[bc * 2 + 1], mx);
        atomicAdd(&g_dsum[bc * 3],     sd);
        atomicAdd(&g_dsum[bc * 3 + 1], sd2);
        atomicAdd(&g_dsum[bc * 3 + 2], spd);
    }

    // ---- last-block-done: compute loss, then reset accumulators ----
    __threadfence();
    __shared__ unsigned done;
    if (j == 0) done = atomicAdd(&g_ctr, 1u);
    __syncthreads();
    if (done == gridDim.x - 1) {
        __threadfence();
        __shared__ float sfin[BC];
        if (j < BC) {
            const float dmin = g_minmax[j * 2];
            const float dmax = g_minmax[j * 2 + 1];
            const float inv  = 1.0f / (dmax - dmin + 1e-8f);
            const float Sd   = g_dsum[j * 3];
            const float Sd2  = g_dsum[j * 3 + 1];
            const float Spd  = g_dsum[j * 3 + 2];
            const float Sp   = g_sums[j * 2];
            const float Sp2  = g_sums[j * 2 + 1];
            const float I  = inv * (Spd - dmin * Sp);
            const float D2 = inv * inv * (Sd2 - 2.0f * dmin * Sd + 65536.0f * dmin * dmin);
            sfin[j] = 1.0f - 2.0f * I / (Sp2 + D2 + 1e-6f);
        }
        __syncthreads();
        if (j == 0) {
            float acc = 0.0f;
            #pragma unroll
            for (int i = 0; i < BC; ++i) acc += sfin[i];
            out[0] = acc / (float)BC;
        }
        // reset for next graph replay — strided loops cover EVERY element
        for (int k = j; k < BC * 2; k += 256) g_minmax[k] = 0.0f;
        for (int k = j; k < BC * 3; k += 256) g_dsum[k]   = 0.0f;
        for (int k = j; k < BC * 2; k += 256) g_sums[k]   = 0.0f;
        if (j == 0) g_ctr = 0u;
    }
}

extern "C" void kernel_launch(void* const* d_in, const int* in_sizes, int n_in,
                              void* d_out, int out_size) {
    const float* logits  = (const float*)d_in[0];
    const int*   targets = (const int*)d_in[1];
    float* out = (float*)d_out;

    k_pre <<<BC * 2 + BB * 32, 256>>>(targets, logits);
    k_main<<<BC * Hdim / 4, 256>>>(out);
}

// round 15
// speedup vs baseline: 1.4404x; 1.0039x over previous
#include <cuda_runtime.h>
#include <cuda_bf16.h>
#include <math.h>

#define Hdim 256
#define Wdim 256
#define HW   65536
#define CC   12
#define BB   8
#define BC   96
#define SENT 600        // sentinel: 600^2 = 360000 > max real d^2 (130050)

#define PQ_SCALE 65535.0f
#define PQ_INV   (1.0f / 65535.0f)

// Scratch (device globals; no allocation allowed).
// Accumulators are ZERO-initialized at module load and reset to zero by the
// last k_main block each run -> every graph replay sees identical state.
__device__ unsigned short g_vU[BC * HW]; // up-scan:  dist | (fg<<15)
__device__ unsigned short g_vD[BC * HW]; // down-scan: dist
__device__ unsigned short g_p [BC * HW]; // quantized softmax probs
__device__ int   g_hasfg[BC];            // plain stores, rewritten each run
__device__ float g_minmax[BC * 2];       // (min<=0, max>=0) per bc -- atomic
__device__ float g_dsum  [BC * 3];       // (sum d, sum d^2, sum p*d) -- atomic
__device__ float g_sums  [BC * 2];       // (sum p, sum p^2) -- atomic
__device__ unsigned g_ctr;               // k_main completion counter

__device__ __forceinline__ float atomicMinFloat(float* a, float v) {
    return (v >= 0.0f)
        ? __int_as_float(atomicMin((int*)a, __float_as_int(v)))
        : __uint_as_float(atomicMax((unsigned*)a, __float_as_uint(v)));
}
__device__ __forceinline__ float atomicMaxFloat(float* a, float v) {
    return (v >= 0.0f)
        ? __int_as_float(atomicMax((int*)a, __float_as_int(v)))
        : __uint_as_float(atomicMin((unsigned*)a, __float_as_uint(v)));
}

// ---------------------------------------------------------------------------
// K1: fused "preparation" kernel, 448 blocks (unchanged from R14).
//  blocks [0,192):   vertical 1D distance scans ((bc, dir) split)
//  blocks [192,448): softmax over C per pixel; p stored u16, Sp/Sp2 atomics.
// ---------------------------------------------------------------------------
__global__ void __launch_bounds__(256) k_pre(const int* __restrict__ targets,
                                             const float* __restrict__ logits) {
    if (blockIdx.x < BC * 2) {
        const int bc  = blockIdx.x >> 1;
        const int dir = blockIdx.x & 1;
        const int b   = bc / CC, c = bc % CC;
        const int w   = threadIdx.x;
        const int* tb = targets + b * HW;

        if (dir == 0) {
            unsigned short* V = g_vU + bc * HW;
            int upP = -100000;   // last bg row (zero of m)
            int upN = -100000;   // last fg row (zero of ~m)
            int anyfg = 0;
            #pragma unroll 16
            for (int h = 0; h < Hdim; ++h) {
                const int fg = (tb[h * Wdim + w] == c);
                anyfg |= fg;
                if (!fg) upP = h;
                else     upN = h;
                const int d = fg ? min(h - upP, SENT) : min(h - upN, SENT);
                V[h * Wdim + w] = (unsigned short)(d | (fg << 15));
            }
            const int blkfg = __syncthreads_or(anyfg);
            if (w == 0) g_hasfg[bc] = blkfg;
        } else {
            unsigned short* V = g_vD + bc * HW;
            int dnP = 100000, dnN = 100000;
            #pragma unroll 16
            for (int h = Hdim - 1; h >= 0; --h) {
                const int fg = (tb[h * Wdim + w] == c);
                if (!fg) dnP = h;
                else     dnN = h;
                const int d = fg ? min(dnP - h, SENT) : min(dnN - h, SENT);
                V[h * Wdim + w] = (unsigned short)d;
            }
        }
    } else {
        const int blkp = blockIdx.x - BC * 2;  // b*32 + rowgroup
        const int b    = blkp >> 5;
        const int h0   = (blkp & 31) * 8;
        const int w    = threadIdx.x;

        float aS[CC], aP2[CC];
        #pragma unroll
        for (int c = 0; c < CC; ++c) { aS[c] = 0.0f; aP2[c] = 0.0f; }

        const int boff = b * CC * HW;
        for (int r = 0; r < 8; ++r) {
            const int pix = (h0 + r) * Wdim + w;
            float l[CC];
            float mxl = -1e30f;
            #pragma unroll
            for (int c = 0; c < CC; ++c) {
                l[c] = logits[boff + c * HW + pix];
                mxl = fmaxf(mxl, l[c]);
            }
            float s = 0.0f;
            #pragma unroll
            for (int c = 0; c < CC; ++c) { l[c] = __expf(l[c] - mxl); s += l[c]; }
            const float rs = 1.0f / s;
            #pragma unroll
            for (int c = 0; c < CC; ++c) {
                const float p = l[c] * rs;
                g_p[boff + c * HW + pix] =
                    (unsigned short)__float2uint_rn(p * PQ_SCALE);
                aS [c] += p;
                aP2[c] = fmaf(p, p, aP2[c]);
            }
        }

        #pragma unroll
        for (int c = 0; c < CC; ++c) {
            #pragma unroll
            for (int o = 16; o; o >>= 1) {
                aS [c] += __shfl_xor_sync(0xffffffffu, aS [c], o);
                aP2[c] += __shfl_xor_sync(0xffffffffu, aP2[c], o);
            }
        }
        __shared__ float sred[24][8];
        const int lane = w & 31, wi = w >> 5;
        if (lane == 0) {
            #pragma unroll
            for (int c = 0; c < CC; ++c) {
                sred[c * 2 + 0][wi] = aS [c];
                sred[c * 2 + 1][wi] = aP2[c];
            }
        }
        __syncthreads();
        if (w < 24) {
            float acc = 0.0f;
            #pragma unroll
            for (int i = 0; i < 8; ++i) acc += sred[w][i];
            atomicAdd(&g_sums[(b * CC + (w >> 1)) * 2 + (w & 1)], acc);
        }
    }
}

// ---------------------------------------------------------------------------
// K2: horizontal exact min-plus, 4 rows/block; dt in registers only.
// Padded smem (±256 = +INF) -> probes need NO index clamping; 2 radii per
// exit check. Over-probing is safe: every candidate is a genuine
// (j-k)^2 + g2 term (or +1e9 pad), so best never undershoots -> exact.
// Per thread: min, max, sum d, sum d^2, sum p*d; one block reduction +
// 5 atomics per 4 rows. Last block computes the loss and resets ALL
// accumulators (strided loops) for the next graph replay.
// ---------------------------------------------------------------------------
__global__ void __launch_bounds__(256) k_main(float* __restrict__ out) {
    const int row0 = blockIdx.x << 2;      // first of 4 rows (same bc: 256|4)
    const int bc   = row0 >> 8;
    const int j    = threadIdx.x;

    // sm[row*2 + arr][768]: [0,256)=pad, [256,512)=real, [512,768)=pad
    __shared__ __align__(16) float sm[8][768];

    // vectorized pad fill: 8 segments x 128 pad-float4 = 1024 -> 4 per thread
    {
        float4* p4 = (float4*)sm;
        const float4 big = make_float4(1.0e9f, 1.0e9f, 1.0e9f, 1.0e9f);
        #pragma unroll
        for (int i = 0; i < 4; ++i) {
            const int t   = j + i * 256;   // 0..1023
            const int seg = t >> 7;
            const int off = t & 127;
            p4[seg * 192 + (off < 64 ? off : off + 64)] = big;
        }
    }

    int   fgr [4];
    float fsqr[4], pv[4];
    #pragma unroll
    for (int r = 0; r < 4; ++r) {
        const int gi = (row0 + r) * Wdim + j;
        const unsigned vu = g_vU[gi];
        const unsigned vd = g_vD[gi];
        const int   fgk = (int)(vu >> 15);
        const float dd  = (float)min((int)(vu & 0x7fffu), (int)vd);
        const float sq  = dd * dd;
        sm[r * 2 + 0][256 + j] = fgk ? sq : 0.0f;
        sm[r * 2 + 1][256 + j] = fgk ? 0.0f : sq;
        fgr [r] = fgk;
        fsqr[r] = sq;
        pv  [r] = (float)g_p[gi] * PQ_INV;
    }
    const int hf = g_hasfg[bc];
    __syncthreads();

    float mn = 0.0f, mx = 0.0f, sd = 0.0f, sd2 = 0.0f, spd = 0.0f;
    #pragma unroll
    for (int r = 0; r < 4; ++r) {
        const float* s = &sm[r * 2 + (fgr[r] ? 0 : 1)][256 + j];
        float best = fsqr[r];
        float rr = 1.0f, rr1 = 4.0f, f4 = 4.0f;   // r^2, (r+1)^2, 4r @ r=1
        #pragma unroll 1
        for (int t = 1; t < 256; t += 2) {
            if (rr >= best) break;
            const float a = fminf(rr  + s[-t],     rr  + s[t]);
            const float b = fminf(rr1 + s[-t - 1], rr1 + s[t + 1]);
            best = fminf(best, fminf(a, b));
            rr  += f4 + 4.0f;
            rr1 += f4 + 8.0f;
            f4  += 8.0f;
        }
        float dt = fgr[r] ? -sqrtf(best) : sqrtf(best);
        if (!hf) dt = 0.0f;
        mn  = fminf(mn, dt);
        mx  = fmaxf(mx, dt);
        sd  += dt;
        sd2 += dt * dt;
        spd = fmaf(pv[r], dt, spd);
    }

    #pragma unroll
    for (int o = 16; o; o >>= 1) {
        mn  = fminf(mn, __shfl_xor_sync(0xffffffffu, mn, o));
        mx  = fmaxf(mx, __shfl_xor_sync(0xffffffffu, mx, o));
        sd  += __shfl_xor_sync(0xffffffffu, sd,  o);
        sd2 += __shfl_xor_sync(0xffffffffu, sd2, o);
        spd += __shfl_xor_sync(0xffffffffu, spd, o);
    }
    __shared__ float red[5][8];
    const int wid = j >> 5, lane = j & 31;
    if (lane == 0) {
        red[0][wid] = mn; red[1][wid] = mx;
        red[2][wid] = sd; red[3][wid] = sd2; red[4][wid] = spd;
    }
    __syncthreads();
    if (j == 0) {
        mn = red[0][0]; mx = red[1][0]; sd = red[2][0]; sd2 = red[3][0]; spd = red[4][0];
        #pragma unroll
        for (int i = 1; i < 8; ++i) {
            mn  = fminf(mn, red[0][i]);
            mx  = fmaxf(mx, red[1][i]);
            sd  += red[2][i];
            sd2 += red[3][i];
            spd += red[4][i];
        }
        atomicMinFloat(&g_minmax[bc * 2],     mn);
        atomicMaxFloat(&g_minmax[bc * 2 + 1], mx);
        atomicAdd(&g_dsum[bc * 3],     sd);
        atomicAdd(&g_dsum[bc * 3 + 1], sd2);
        atomicAdd(&g_dsum[bc * 3 + 2], spd);
    }

    // ---- last-block-done: compute loss, then reset accumulators ----
    __threadfence();
    __shared__ unsigned done;
    if (j == 0) done = atomicAdd(&g_ctr, 1u);
    __syncthreads();
    if (done == gridDim.x - 1) {
        __threadfence();
        __shared__ float sfin[BC];
        if (j < BC) {
            const float dmin = g_minmax[j * 2];
            const float dmax = g_minmax[j * 2 + 1];
            const float inv  = 1.0f / (dmax - dmin + 1e-8f);
            const float Sd   = g_dsum[j * 3];
            const float Sd2  = g_dsum[j * 3 + 1];
            const float Spd  = g_dsum[j * 3 + 2];
            const float Sp   = g_sums[j * 2];
            const float Sp2  = g_sums[j * 2 + 1];
            const float I  = inv * (Spd - dmin * Sp);
            const float D2 = inv * inv * (Sd2 - 2.0f * dmin * Sd + 65536.0f * dmin * dmin);
            sfin[j] = 1.0f - 2.0f * I / (Sp2 + D2 + 1e-6f);
        }
        __syncthreads();
        if (j == 0) {
            float acc = 0.0f;
            #pragma unroll
            for (int i = 0; i < BC; ++i) acc += sfin[i];
            out[0] = acc / (float)BC;
        }
        // reset for next graph replay — strided loops cover EVERY element
        for (int k = j; k < BC * 2; k += 256) g_minmax[k] = 0.0f;
        for (int k = j; k < BC * 3; k += 256) g_dsum[k]   = 0.0f;
        for (int k = j; k < BC * 2; k += 256) g_sums[k]   = 0.0f;
        if (j == 0) g_ctr = 0u;
    }
}

extern "C" void kernel_launch(void* const* d_in, const int* in_sizes, int n_in,
                              void* d_out, int out_size) {
    const float* logits  = (const float*)d_in[0];
    const int*   targets = (const int*)d_in[1];
    float* out = (float*)d_out;

    k_pre <<<BC * 2 + BB * 32, 256>>>(targets, logits);
    k_main<<<BC * Hdim / 4, 256>>>(out);
}